// round 14
// baseline (speedup 1.0000x reference)
#include <cuda_runtime.h>
#include <math.h>

// ---------------- problem constants ----------------
#define NB    32
#define NSEQ  720
#define NPRED 96
#define NENC  321
#define NROWS (NB * NENC)      // 10272 sequences

#define D0 512
#define S0 48
#define T0 15
#define SY0 2

#define D1 256
#define S1 24
#define T1 4                   // only segments 0..3 are ever consumed
#define STEPS1 60
#define SY1 4

// ---------------- scratch (device globals) ----------------
__device__ __align__(16) float g_xc   [NROWS * NSEQ];
__device__ __align__(16) float g_xe0  [(size_t)T0 * NROWS * D0];
__device__ __align__(16) float g_gi0  [(size_t)T0 * NROWS * 3 * D0];
__device__ __align__(16) float g_h0a  [NROWS * D0];
__device__ __align__(16) float g_h0b  [NROWS * D0];
__device__ __align__(16) float g_xe1  [(size_t)T1 * NROWS * D1];
__device__ __align__(16) float g_gi1  [(size_t)T1 * NROWS * 3 * D1];
__device__ __align__(16) float g_h1a  [NROWS * D1];
__device__ __align__(16) float g_h1b  [NROWS * D1];
__device__ __align__(16) float g_ghd0 [NROWS * 3 * D0];
__device__ __align__(16) float g_gid0 [SY0 * NENC * 3 * D0];
__device__ __align__(16) float g_posx0[SY0 * NENC * D0];
__device__ __align__(16) float g_hy0  [(size_t)SY0 * NROWS * D0];
__device__ __align__(16) float g_ghd1 [NROWS * 3 * D1];
__device__ __align__(16) float g_gid1 [SY1 * NENC * 3 * D1];
__device__ __align__(16) float g_posx1[SY1 * NENC * D1];
__device__ __align__(16) float g_hy1  [(size_t)SY1 * NROWS * D1];

// ---------------- streams/events (created at static-init) ----------------
struct StreamPack {
    cudaStream_t a, b;
    cudaEvent_t root, ea, eb;
    StreamPack() {
        cudaStreamCreateWithFlags(&a, cudaStreamNonBlocking);
        cudaStreamCreateWithFlags(&b, cudaStreamNonBlocking);
        cudaEventCreateWithFlags(&root, cudaEventDisableTiming);
        cudaEventCreateWithFlags(&ea, cudaEventDisableTiming);
        cudaEventCreateWithFlags(&eb, cudaEventDisableTiming);
    }
};
static StreamPack g_sp;

// ---------------- mma / cp.async helpers ----------------
__device__ __forceinline__ void mma8(float c[4], unsigned a0, unsigned a1, unsigned a2,
                                     unsigned a3, unsigned b0, unsigned b1) {
    asm volatile(
        "mma.sync.aligned.m16n8k8.row.col.f32.tf32.tf32.f32 "
        "{%0,%1,%2,%3},{%4,%5,%6,%7},{%8,%9},{%0,%1,%2,%3};"
        : "+f"(c[0]), "+f"(c[1]), "+f"(c[2]), "+f"(c[3])
        : "r"(a0), "r"(a1), "r"(a2), "r"(a3), "r"(b0), "r"(b1));
}
__device__ __forceinline__ void cp16(void* sm, const void* gp, bool pred) {
    unsigned sa = (unsigned)__cvta_generic_to_shared(sm);
    int sz = pred ? 16 : 0;
    asm volatile("cp.async.cg.shared.global [%0], [%1], 16, %2;\n"
                 :: "r"(sa), "l"(gp), "r"(sz));
}
__device__ __forceinline__ void cp_commit() {
    asm volatile("cp.async.commit_group;\n");
}
template <int N>
__device__ __forceinline__ void cp_wait() {
    asm volatile("cp.async.wait_group %0;\n" :: "n"(N));
}

// ---------------- prep: xc[n][t] = x[b][t][e] - x[b][719][e] ----------------
__global__ void prep_kernel(const float* __restrict__ x) {
    __shared__ float tile[32][33];
    int b  = blockIdx.z;
    int t0 = blockIdx.x * 32;
    int e0 = blockIdx.y * 32;
    int tx = threadIdx.x, ty = threadIdx.y;   // (32, 8)
    int e_r = e0 + tx;
    float last = 0.f;
    if (e_r < NENC) last = x[((size_t)b * NSEQ + (NSEQ - 1)) * NENC + e_r];
    #pragma unroll
    for (int l = 0; l < 32; l += 8) {
        int t = t0 + ty + l;
        if (t < NSEQ && e_r < NENC)
            tile[ty + l][tx] = x[((size_t)b * NSEQ + t) * NENC + e_r] - last;
    }
    __syncthreads();
    int t_w = t0 + tx;
    #pragma unroll
    for (int l = 0; l < 32; l += 8) {
        int e = e0 + ty + l;
        if (e < NENC && t_w < NSEQ)
            g_xc[((size_t)b * NENC + e) * NSEQ + t_w] = tile[tx][ty + l];
    }
}

// ---------------- out init ----------------
__global__ void outinit_kernel(const float* __restrict__ x, float* __restrict__ out) {
    int idx = blockIdx.x * blockDim.x + threadIdx.x;
    if (idx >= NB * NPRED * NENC) return;
    int b = idx / (NPRED * NENC);
    int e = idx % NENC;
    out[idx] = x[((size_t)b * NSEQ + (NSEQ - 1)) * NENC + e];
}

// ---------------- embedding (fp32 SIMT; small K) ----------------
template <int SLEN>
__global__ __launch_bounds__(256) void embed_kernel(const float* __restrict__ Wemb,
                                                    const float* __restrict__ bemb,
                                                    float* __restrict__ xe, int d) {
    __shared__ float As[64][SLEN];
    __shared__ float Ws[64][SLEN + 1];
    int seg = blockIdx.z;
    int m0  = blockIdx.x * 64;
    int c0  = blockIdx.y * 64;
    int tid = threadIdx.x;
    for (int e = tid; e < 64 * SLEN; e += 256) {
        int r = e / SLEN, k = e % SLEN;
        int n = m0 + r;
        As[r][k] = (n < NROWS) ? g_xc[(size_t)n * NSEQ + seg * SLEN + k] : 0.f;
    }
    for (int e = tid; e < 64 * SLEN; e += 256) {
        int r = e / SLEN, k = e % SLEN;
        Ws[r][k] = Wemb[(size_t)(c0 + r) * SLEN + k];
    }
    __syncthreads();
    int tx = tid % 16, ty = tid / 16;
    float acc[4][4] = {};
    for (int k = 0; k < SLEN; k++) {
        float a[4], w[4];
        #pragma unroll
        for (int i = 0; i < 4; i++) a[i] = As[ty * 4 + i][k];
        #pragma unroll
        for (int j = 0; j < 4; j++) w[j] = Ws[tx * 4 + j][k];
        #pragma unroll
        for (int i = 0; i < 4; i++)
            #pragma unroll
            for (int j = 0; j < 4; j++) acc[i][j] += a[i] * w[j];
    }
    #pragma unroll
    for (int i = 0; i < 4; i++) {
        int n = m0 + ty * 4 + i;
        if (n >= NROWS) continue;
        #pragma unroll
        for (int j = 0; j < 4; j++) {
            int c = c0 + tx * 4 + j;
            float v = acc[i][j] + bemb[c];
            xe[((size_t)seg * NROWS + n) * d + c] = v > 0.f ? v : 0.f;
        }
    }
}

// ---------------- SIMT GEMM (MODE 2 = scatter-accumulate 0.5*v into output) ----------------
template <int MODE>
__global__ __launch_bounds__(256) void gemm_nt(const float* __restrict__ A, int lda,
                                               const float* __restrict__ Bw, int ldb,
                                               const float* __restrict__ bias,
                                               float* __restrict__ C, int ldc,
                                               int M, int Ncols, int K,
                                               float* __restrict__ out, int s_len) {
    __shared__ float As[16][64 + 4];
    __shared__ float Bs[16][64 + 4];
    int m0  = blockIdx.y * 64;
    int c0  = blockIdx.x * 64;
    int tid = threadIdx.x;
    int tx  = tid % 16, ty = tid / 16;
    int lr  = tid / 4;
    int lk  = (tid % 4) * 4;
    const float* Aptr = A + (size_t)(m0 + lr) * lda + lk;
    const float* Bptr = Bw + (size_t)(c0 + lr) * ldb + lk;
    bool a_ok = (m0 + lr) < M;
    bool b_ok = (c0 + lr) < Ncols;
    float acc[4][4] = {};
    for (int k0 = 0; k0 < K; k0 += 16) {
        float4 av = a_ok ? *(const float4*)(Aptr + k0) : make_float4(0, 0, 0, 0);
        float4 bv = b_ok ? *(const float4*)(Bptr + k0) : make_float4(0, 0, 0, 0);
        As[lk + 0][lr] = av.x; As[lk + 1][lr] = av.y; As[lk + 2][lr] = av.z; As[lk + 3][lr] = av.w;
        Bs[lk + 0][lr] = bv.x; Bs[lk + 1][lr] = bv.y; Bs[lk + 2][lr] = bv.z; Bs[lk + 3][lr] = bv.w;
        __syncthreads();
        #pragma unroll
        for (int kk = 0; kk < 16; kk++) {
            float a[4], b[4];
            #pragma unroll
            for (int i = 0; i < 4; i++) a[i] = As[kk][ty * 4 + i];
            #pragma unroll
            for (int j = 0; j < 4; j++) b[j] = Bs[kk][tx * 4 + j];
            #pragma unroll
            for (int i = 0; i < 4; i++)
                #pragma unroll
                for (int j = 0; j < 4; j++) acc[i][j] += a[i] * b[j];
        }
        __syncthreads();
    }
    #pragma unroll
    for (int i = 0; i < 4; i++) {
        int m = m0 + ty * 4 + i;
        if (m >= M) continue;
        #pragma unroll
        for (int j = 0; j < 4; j++) {
            int c = c0 + tx * 4 + j;
            if (c >= Ncols) continue;
            float v = acc[i][j] + (bias ? bias[c] : 0.f);
            if (MODE == 0) {
                C[(size_t)m * ldc + c] = v;
            } else {
                int sy = m / NROWS;
                int n  = m % NROWS;
                int b  = n / NENC, e = n % NENC;
                int p  = sy * s_len + c;
                out[((size_t)b * NPRED + p) * NENC + e] += 0.5f * v;
            }
        }
    }
}

// ---------------- tf32 tensor-core GEMM with cp.async double buffering (BK=16) ----------------
__global__ __launch_bounds__(256) void gemm_tf32(const float* __restrict__ A, int lda,
                                                 const float* __restrict__ Bw, int ldb,
                                                 const float* __restrict__ bias,
                                                 float* __restrict__ C, int ldc,
                                                 int M, int Ncols, int K) {
    __shared__ __align__(16) unsigned As[2][128][20];
    __shared__ __align__(16) unsigned Bs[2][128][20];
    int m0 = blockIdx.y * 128, c0 = blockIdx.x * 128;
    int tid = threadIdx.x, lane = tid & 31, warp = tid >> 5;
    int g = lane >> 2, tig = lane & 3;
    int wm = (warp >> 2) * 64, wn = (warp & 3) * 32;
    float acc[4][4][4] = {};

    int r0l = tid >> 2, kcl = (tid & 3) * 4;
    int r1l = r0l + 64;
    const float* Ap0 = A + (size_t)(m0 + r0l) * lda + kcl;
    const float* Ap1 = A + (size_t)(m0 + r1l) * lda + kcl;
    const float* Bp0 = Bw + (size_t)(c0 + r0l) * ldb + kcl;
    const float* Bp1 = Bw + (size_t)(c0 + r1l) * ldb + kcl;
    bool a0ok = (m0 + r0l) < M, a1ok = (m0 + r1l) < M;
    bool b0ok = (c0 + r0l) < Ncols, b1ok = (c0 + r1l) < Ncols;

    int nit = K / 16;
    cp16(&As[0][r0l][kcl], Ap0, a0ok);
    cp16(&As[0][r1l][kcl], Ap1, a1ok);
    cp16(&Bs[0][r0l][kcl], Bp0, b0ok);
    cp16(&Bs[0][r1l][kcl], Bp1, b1ok);
    cp_commit();

    for (int it = 0; it < nit; it++) {
        if (it + 1 < nit) {
            int koff = (it + 1) * 16;
            int nb = (it + 1) & 1;
            cp16(&As[nb][r0l][kcl], Ap0 + koff, a0ok);
            cp16(&As[nb][r1l][kcl], Ap1 + koff, a1ok);
            cp16(&Bs[nb][r0l][kcl], Bp0 + koff, b0ok);
            cp16(&Bs[nb][r1l][kcl], Bp1 + koff, b1ok);
            cp_commit();
            cp_wait<1>();
        } else {
            cp_wait<0>();
        }
        __syncthreads();
        int cb = it & 1;
        #pragma unroll
        for (int ks = 0; ks < 2; ks++) {
            unsigned af[4][4];
            #pragma unroll
            for (int mt = 0; mt < 4; mt++) {
                int r = wm + mt * 16 + g;
                af[mt][0] = As[cb][r][ks * 8 + tig];
                af[mt][1] = As[cb][r + 8][ks * 8 + tig];
                af[mt][2] = As[cb][r][ks * 8 + tig + 4];
                af[mt][3] = As[cb][r + 8][ks * 8 + tig + 4];
            }
            #pragma unroll
            for (int nt = 0; nt < 4; nt++) {
                int cc = wn + nt * 8 + g;
                unsigned b0 = Bs[cb][cc][ks * 8 + tig];
                unsigned b1 = Bs[cb][cc][ks * 8 + tig + 4];
                #pragma unroll
                for (int mt = 0; mt < 4; mt++)
                    mma8(acc[mt][nt], af[mt][0], af[mt][1], af[mt][2], af[mt][3], b0, b1);
            }
        }
        __syncthreads();
    }

    #pragma unroll
    for (int mt = 0; mt < 4; mt++)
        #pragma unroll
        for (int rh = 0; rh < 2; rh++) {
            int m = m0 + wm + mt * 16 + g + rh * 8;
            if (m >= M) continue;
            #pragma unroll
            for (int nt = 0; nt < 4; nt++) {
                int c = c0 + wn + nt * 8 + tig * 2;
                if (c >= Ncols) continue;
                float v0 = acc[mt][nt][rh * 2 + 0] + (bias ? bias[c] : 0.f);
                if (c + 1 < Ncols) {
                    float v1 = acc[mt][nt][rh * 2 + 1] + (bias ? bias[c + 1] : 0.f);
                    *(float2*)(C + (size_t)m * ldc + c) = make_float2(v0, v1);
                } else {
                    C[(size_t)m * ldc + c] = v0;
                }
            }
        }
}

// ---------------- fused tf32 GRU step (launch-per-step; layer 0 only) ----------------
template <int D>
__global__ __launch_bounds__(256) void gru_step_tf32(const float* __restrict__ h_in,
                                                     const float* __restrict__ Whh,
                                                     const float* __restrict__ bhh,
                                                     const float* __restrict__ gi,
                                                     float* __restrict__ h_out, int M) {
    __shared__ __align__(16) unsigned Hs[2][64][20];
    __shared__ __align__(16) unsigned Ws[2][3][64][20];
    int m0 = blockIdx.y * 64, c0 = blockIdx.x * 64;
    int tid = threadIdx.x, lane = tid & 31, warp = tid >> 5;
    int g = lane >> 2, tig = lane & 3;
    int wm = (warp >> 2) * 32, wn = (warp & 3) * 16;
    float acc[3][2][2][4] = {};

    int r_st = tid >> 2, kc_st = (tid & 3) * 4;
    const float* Hp = h_in + (size_t)(m0 + r_st) * D + kc_st;
    const float* Wp0 = Whh + (size_t)(0 * D + c0 + r_st) * D + kc_st;
    const float* Wp1 = Whh + (size_t)(1 * D + c0 + r_st) * D + kc_st;
    const float* Wp2 = Whh + (size_t)(2 * D + c0 + r_st) * D + kc_st;
    bool hok = (m0 + r_st) < M;

    const int nit = D / 16;
    cp16(&Hs[0][r_st][kc_st], Hp, hok);
    cp16(&Ws[0][0][r_st][kc_st], Wp0, true);
    cp16(&Ws[0][1][r_st][kc_st], Wp1, true);
    cp16(&Ws[0][2][r_st][kc_st], Wp2, true);
    cp_commit();

    for (int it = 0; it < nit; it++) {
        if (it + 1 < nit) {
            int koff = (it + 1) * 16;
            int nb = (it + 1) & 1;
            cp16(&Hs[nb][r_st][kc_st], Hp + koff, hok);
            cp16(&Ws[nb][0][r_st][kc_st], Wp0 + koff, true);
            cp16(&Ws[nb][1][r_st][kc_st], Wp1 + koff, true);
            cp16(&Ws[nb][2][r_st][kc_st], Wp2 + koff, true);
            cp_commit();
            cp_wait<1>();
        } else {
            cp_wait<0>();
        }
        __syncthreads();
        int cb = it & 1;
        #pragma unroll
        for (int ks = 0; ks < 2; ks++) {
            unsigned af[2][4];
            #pragma unroll
            for (int mt = 0; mt < 2; mt++) {
                int r = wm + mt * 16 + g;
                af[mt][0] = Hs[cb][r][ks * 8 + tig];
                af[mt][1] = Hs[cb][r + 8][ks * 8 + tig];
                af[mt][2] = Hs[cb][r][ks * 8 + tig + 4];
                af[mt][3] = Hs[cb][r + 8][ks * 8 + tig + 4];
            }
            #pragma unroll
            for (int gate = 0; gate < 3; gate++)
                #pragma unroll
                for (int nt = 0; nt < 2; nt++) {
                    int cc = wn + nt * 8 + g;
                    unsigned b0 = Ws[cb][gate][cc][ks * 8 + tig];
                    unsigned b1 = Ws[cb][gate][cc][ks * 8 + tig + 4];
                    #pragma unroll
                    for (int mt = 0; mt < 2; mt++)
                        mma8(acc[gate][mt][nt], af[mt][0], af[mt][1], af[mt][2], af[mt][3],
                             b0, b1);
                }
        }
        __syncthreads();
    }

    float2 br[2], bz[2], bn[2];
    #pragma unroll
    for (int nt = 0; nt < 2; nt++) {
        int c = c0 + wn + nt * 8 + tig * 2;
        br[nt] = *(const float2*)(bhh + c);
        bz[nt] = *(const float2*)(bhh + D + c);
        bn[nt] = *(const float2*)(bhh + 2 * D + c);
    }

    #pragma unroll
    for (int mt = 0; mt < 2; mt++)
        #pragma unroll
        for (int rh = 0; rh < 2; rh++) {
            int m = m0 + wm + mt * 16 + g + rh * 8;
            if (m >= M) continue;
            const float* gim = gi + (size_t)m * 3 * D;
            #pragma unroll
            for (int nt = 0; nt < 2; nt++) {
                int c = c0 + wn + nt * 8 + tig * 2;
                float2 vr = *(const float2*)(gim + c);
                float2 vz = *(const float2*)(gim + D + c);
                float2 vn = *(const float2*)(gim + 2 * D + c);
                float2 hh = *(const float2*)(h_in + (size_t)m * D + c);
                float ar0 = acc[0][mt][nt][rh * 2 + 0], ar1 = acc[0][mt][nt][rh * 2 + 1];
                float az0 = acc[1][mt][nt][rh * 2 + 0], az1 = acc[1][mt][nt][rh * 2 + 1];
                float an0 = acc[2][mt][nt][rh * 2 + 0], an1 = acc[2][mt][nt][rh * 2 + 1];
                float r0 = 1.f / (1.f + __expf(-(vr.x + ar0 + br[nt].x)));
                float r1 = 1.f / (1.f + __expf(-(vr.y + ar1 + br[nt].y)));
                float z0 = 1.f / (1.f + __expf(-(vz.x + az0 + bz[nt].x)));
                float z1 = 1.f / (1.f + __expf(-(vz.y + az1 + bz[nt].y)));
                float n0 = tanhf(vn.x + r0 * (an0 + bn[nt].x));
                float n1 = tanhf(vn.y + r1 * (an1 + bn[nt].y));
                float o0 = (1.f - z0) * n0 + z0 * hh.x;
                float o1 = (1.f - z1) * n1 + z1 * hh.y;
                *(float2*)(h_out + (size_t)m * D + c) = make_float2(o0, o1);
            }
        }
}

// ---------------- layer-1 row-parallel fused scan: all 60 steps, h in smem ----------------
// grid = 147 blocks x 320 thr; block owns 70 rows (padded to 80 = 5 m16 tiles).
// No inter-block deps (rows independent) -> no barrier, plain kernel.
#define SC_ROWS    70
#define SC_TCAP    80
#define SC_THREADS 320
#define SC_HSTR    260
#define SC_HFLOATS (2 * SC_TCAP * SC_HSTR)                // 41600 floats
#define SCAN_SMEM  (SC_HFLOATS * 4 + 2 * 3 * 64 * 20 * 4) // 166400 + 30720 = 197120
#define SCAN_BLOCKS ((NROWS + SC_ROWS - 1) / SC_ROWS)     // 147

__global__ __launch_bounds__(SC_THREADS, 1) void gru_scan_rows(
    const float* __restrict__ Whh, const float* __restrict__ bhh,
    const float* __restrict__ gi_base, float* __restrict__ h_final) {
    extern __shared__ __align__(16) float sm[];
    float*    hb = sm;                                  // [2][80][260]
    unsigned* wb = (unsigned*)(sm + SC_HFLOATS);        // [2][3][64][20]
    const int D = D1;
    int tid = threadIdx.x, lane = tid & 31, warp = tid >> 5;
    int rt = warp >> 1, cp = warp & 1;                  // rowtile 0..4, colpair 0..1
    int g = lane >> 2, tig = lane & 3;
    int row0 = blockIdx.x * SC_ROWS;

    // zero both h buffers (covers pad rows; real rows start at h=0 anyway)
    for (int i = tid; i < SC_HFLOATS; i += SC_THREADS) hb[i] = 0.f;
    __syncthreads();

    int wr = tid >> 2, wk4 = (tid & 3) * 4;             // loader map (tid<256)
    int cur = 0;
    for (int t = 0; t < STEPS1; t++) {
        const float* gi = gi_base + (size_t)(t & 3) * NROWS * 3 * D;
        int nxt = cur ^ 1;
        float* hc = hb + cur * (SC_TCAP * SC_HSTR);
        float* hn = hb + nxt * (SC_TCAP * SC_HSTR);

        for (int ds = 0; ds < 4; ds++) {
            float acc[3][4][4] = {};
            // preload W chunk 0 for this d-slice
            if (tid < 256) {
                #pragma unroll
                for (int gate = 0; gate < 3; gate++)
                    cp16(&wb[((0 * 3 + gate) * 64 + wr) * 20 + wk4],
                         Whh + ((size_t)(gate * D + ds * 64 + wr)) * D + wk4, true);
            }
            cp_commit();
            for (int kc = 0; kc < 16; kc++) {
                if (kc + 1 < 16) {
                    if (tid < 256) {
                        int nb = (kc + 1) & 1;
                        #pragma unroll
                        for (int gate = 0; gate < 3; gate++)
                            cp16(&wb[((nb * 3 + gate) * 64 + wr) * 20 + wk4],
                                 Whh + ((size_t)(gate * D + ds * 64 + wr)) * D +
                                     (kc + 1) * 16 + wk4, true);
                    }
                    cp_commit();
                    cp_wait<1>();
                } else {
                    cp_wait<0>();
                }
                __syncthreads();
                int cb = kc & 1;
                int k0 = kc * 16;
                #pragma unroll
                for (int ks = 0; ks < 2; ks++) {
                    int kk = k0 + ks * 8;
                    const float* hr0 = hc + (rt * 16 + g) * SC_HSTR + kk;
                    const float* hr1 = hr0 + 8 * SC_HSTR;
                    unsigned a0 = __float_as_uint(hr0[tig]);
                    unsigned a1 = __float_as_uint(hr1[tig]);
                    unsigned a2 = __float_as_uint(hr0[tig + 4]);
                    unsigned a3 = __float_as_uint(hr1[tig + 4]);
                    #pragma unroll
                    for (int gate = 0; gate < 3; gate++)
                        #pragma unroll
                        for (int nt = 0; nt < 4; nt++) {
                            int cc = cp * 32 + nt * 8 + g;
                            unsigned b0 = wb[((cb * 3 + gate) * 64 + cc) * 20 + ks * 8 + tig];
                            unsigned b1 = wb[((cb * 3 + gate) * 64 + cc) * 20 + ks * 8 + tig + 4];
                            mma8(acc[gate][nt], a0, a1, a2, a3, b0, b1);
                        }
                }
                __syncthreads();
            }

            // epilogue for this 64-col slice
            #pragma unroll
            for (int rh = 0; rh < 2; rh++) {
                int lr = rt * 16 + g + rh * 8;
                int grow = row0 + lr;
                bool ok = (lr < SC_ROWS) && (grow < NROWS);
                const float* gim = gi + (size_t)grow * 3 * D;
                #pragma unroll
                for (int nt = 0; nt < 4; nt++) {
                    int c = ds * 64 + cp * 32 + nt * 8 + tig * 2;
                    if (!ok) continue;
                    float2 vr = *(const float2*)(gim + c);
                    float2 vz = *(const float2*)(gim + D + c);
                    float2 vn = *(const float2*)(gim + 2 * D + c);
                    float2 bb_r = *(const float2*)(bhh + c);
                    float2 bb_z = *(const float2*)(bhh + D + c);
                    float2 bb_n = *(const float2*)(bhh + 2 * D + c);
                    float h0 = hc[lr * SC_HSTR + c];
                    float h1 = hc[lr * SC_HSTR + c + 1];
                    float ar0 = acc[0][nt][rh * 2 + 0], ar1 = acc[0][nt][rh * 2 + 1];
                    float az0 = acc[1][nt][rh * 2 + 0], az1 = acc[1][nt][rh * 2 + 1];
                    float an0 = acc[2][nt][rh * 2 + 0], an1 = acc[2][nt][rh * 2 + 1];
                    float r0 = 1.f / (1.f + __expf(-(vr.x + ar0 + bb_r.x)));
                    float r1 = 1.f / (1.f + __expf(-(vr.y + ar1 + bb_r.y)));
                    float z0 = 1.f / (1.f + __expf(-(vz.x + az0 + bb_z.x)));
                    float z1 = 1.f / (1.f + __expf(-(vz.y + az1 + bb_z.y)));
                    float n0 = tanhf(vn.x + r0 * (an0 + bb_n.x));
                    float n1 = tanhf(vn.y + r1 * (an1 + bb_n.y));
                    float o0 = (1.f - z0) * n0 + z0 * h0;
                    float o1 = (1.f - z1) * n1 + z1 * h1;
                    hn[lr * SC_HSTR + c]     = o0;
                    hn[lr * SC_HSTR + c + 1] = o1;
                    if (t == STEPS1 - 1)
                        *(float2*)(h_final + (size_t)grow * D + c) = make_float2(o0, o1);
                }
            }
            __syncthreads();   // writes to hn / reads of wb done before next slice preload
        }
        cur ^= 1;
    }
}

// ---------------- decoder position rows ----------------
__global__ void posx_kernel(const float* __restrict__ pos, const float* __restrict__ chan,
                            float* __restrict__ posx, int D, int S) {
    int total = S * NENC * D;
    for (int idx = blockIdx.x * blockDim.x + threadIdx.x; idx < total;
         idx += gridDim.x * blockDim.x) {
        int r = idx / D, j = idx % D;
        int sy = r / NENC, e = r % NENC;
        int half = D / 2;
        posx[idx] = (j < half) ? pos[sy * half + j] : chan[e * half + (j - half)];
    }
}

// ---------------- decoder combine ----------------
__global__ void hy_kernel(const float* __restrict__ gid, const float* __restrict__ ghd,
                          const float* __restrict__ hfin, float* __restrict__ hy,
                          int D, int S) {
    size_t total = (size_t)S * NROWS * D;
    for (size_t idx = (size_t)blockIdx.x * blockDim.x + threadIdx.x; idx < total;
         idx += (size_t)gridDim.x * blockDim.x) {
        int j   = (int)(idx % D);
        size_t r = idx / D;
        int n   = (int)(r % NROWS);
        int sy  = (int)(r / NROWS);
        int e   = n % NENC;
        const float* gi = gid + (size_t)(sy * NENC + e) * 3 * D;
        const float* gh = ghd + (size_t)n * 3 * D;
        float rr = 1.f / (1.f + __expf(-(gi[j] + gh[j])));
        float zz = 1.f / (1.f + __expf(-(gi[D + j] + gh[D + j])));
        float nn = tanhf(gi[2 * D + j] + rr * gh[2 * D + j]);
        float h  = hfin[(size_t)n * D + j];
        hy[idx]  = (1.f - zz) * nn + zz * h;
    }
}

// ---------------- host orchestration (fork-join, two layers in parallel) ----------------
static inline int ceildiv(int a, int b) { return (a + b - 1) / b; }

extern "C" void kernel_launch(void* const* d_in, const int* in_sizes, int n_in,
                              void* d_out, int out_size) {
    const float* x      = (const float*)d_in[0];
    const float* Wemb0  = (const float*)d_in[1];
    const float* bemb0  = (const float*)d_in[2];
    const float* Wih0   = (const float*)d_in[3];
    const float* Whh0   = (const float*)d_in[4];
    const float* bih0   = (const float*)d_in[5];
    const float* bhh0   = (const float*)d_in[6];
    const float* Wpred0 = (const float*)d_in[7];
    const float* bpred0 = (const float*)d_in[8];
    const float* pos0   = (const float*)d_in[9];
    const float* chan0  = (const float*)d_in[10];
    const float* Wemb1  = (const float*)d_in[11];
    const float* bemb1  = (const float*)d_in[12];
    const float* Wih1   = (const float*)d_in[13];
    const float* Whh1   = (const float*)d_in[14];
    const float* bih1   = (const float*)d_in[15];
    const float* bhh1   = (const float*)d_in[16];
    const float* Wpred1 = (const float*)d_in[17];
    const float* bpred1 = (const float*)d_in[18];
    const float* pos1   = (const float*)d_in[19];
    const float* chan1  = (const float*)d_in[20];
    float* out = (float*)d_out;

    float *xe0, *gi0, *h0a, *h0b, *xe1, *gi1, *h1a;
    float *ghd0, *gid0, *posx0, *hy0, *ghd1, *gid1, *posx1, *hy1;
    cudaGetSymbolAddress((void**)&xe0, g_xe0);
    cudaGetSymbolAddress((void**)&gi0, g_gi0);
    cudaGetSymbolAddress((void**)&h0a, g_h0a);
    cudaGetSymbolAddress((void**)&h0b, g_h0b);
    cudaGetSymbolAddress((void**)&xe1, g_xe1);
    cudaGetSymbolAddress((void**)&gi1, g_gi1);
    cudaGetSymbolAddress((void**)&h1a, g_h1a);
    cudaGetSymbolAddress((void**)&ghd0, g_ghd0);
    cudaGetSymbolAddress((void**)&gid0, g_gid0);
    cudaGetSymbolAddress((void**)&posx0, g_posx0);
    cudaGetSymbolAddress((void**)&hy0, g_hy0);
    cudaGetSymbolAddress((void**)&ghd1, g_ghd1);
    cudaGetSymbolAddress((void**)&gid1, g_gid1);
    cudaGetSymbolAddress((void**)&posx1, g_posx1);
    cudaGetSymbolAddress((void**)&hy1, g_hy1);

    cudaFuncSetAttribute(gru_scan_rows, cudaFuncAttributeMaxDynamicSharedMemorySize,
                         SCAN_SMEM);

    cudaStream_t sA = g_sp.a, sB = g_sp.b;
    int rb64  = ceildiv(NROWS, 64);    // 161
    int rb128 = ceildiv(NROWS, 128);   // 81

    // ---- prologue on main stream: xc + out init ----
    prep_kernel<<<dim3(ceildiv(NSEQ, 32), ceildiv(NENC, 32), NB), dim3(32, 8)>>>(x);
    outinit_kernel<<<ceildiv(NB * NPRED * NENC, 256), 256>>>(x, out);

    // ---- fork ----
    cudaEventRecord(g_sp.root, 0);
    cudaStreamWaitEvent(sA, g_sp.root, 0);
    cudaStreamWaitEvent(sB, g_sp.root, 0);

    // ---------- layer 0 chain on stream A ----------
    embed_kernel<S0><<<dim3(rb64, D0 / 64, T0), 256, 0, sA>>>(Wemb0, bemb0, xe0, D0);
    gemm_tf32<<<dim3(3 * D0 / 128, ceildiv(T0 * NROWS, 128)), 256, 0, sA>>>(
        xe0, D0, Wih0, D0, bih0, gi0, 3 * D0, T0 * NROWS, 3 * D0, D0);
    cudaMemsetAsync(h0a, 0, (size_t)NROWS * D0 * sizeof(float), sA);
    {
        float* hin = h0a; float* hout = h0b;
        for (int t = 0; t < T0; t++) {
            gru_step_tf32<D0><<<dim3(D0 / 64, rb64), 256, 0, sA>>>(
                hin, Whh0, bhh0, gi0 + (size_t)t * NROWS * 3 * D0, hout, NROWS);
            float* tmp = hin; hin = hout; hout = tmp;
        }
        gemm_tf32<<<dim3(3 * D0 / 128, rb128), 256, 0, sA>>>(
            hin, D0, Whh0, D0, bhh0, ghd0, 3 * D0, NROWS, 3 * D0, D0);
        posx_kernel<<<ceildiv(SY0 * NENC * D0, 256), 256, 0, sA>>>(pos0, chan0, posx0, D0, SY0);
        gemm_tf32<<<dim3(3 * D0 / 128, ceildiv(SY0 * NENC, 128)), 256, 0, sA>>>(
            posx0, D0, Wih0, D0, bih0, gid0, 3 * D0, SY0 * NENC, 3 * D0, D0);
        hy_kernel<<<4096, 256, 0, sA>>>(gid0, ghd0, hin, hy0, D0, SY0);
    }

    // ---------- layer 1 chain on stream B ----------
    embed_kernel<S1><<<dim3(rb64, D1 / 64, T1), 256, 0, sB>>>(Wemb1, bemb1, xe1, D1);
    gemm_tf32<<<dim3(3 * D1 / 128, ceildiv(T1 * NROWS, 128)), 256, 0, sB>>>(
        xe1, D1, Wih1, D1, bih1, gi1, 3 * D1, T1 * NROWS, 3 * D1, D1);
    // fused 60-step scan: one launch, h resident in smem, rows independent
    gru_scan_rows<<<SCAN_BLOCKS, SC_THREADS, SCAN_SMEM, sB>>>(Whh1, bhh1, gi1, h1a);
    gemm_tf32<<<dim3(3 * D1 / 128, rb128), 256, 0, sB>>>(
        h1a, D1, Whh1, D1, bhh1, ghd1, 3 * D1, NROWS, 3 * D1, D1);
    posx_kernel<<<ceildiv(SY1 * NENC * D1, 256), 256, 0, sB>>>(pos1, chan1, posx1, D1, SY1);
    gemm_tf32<<<dim3(3 * D1 / 128, ceildiv(SY1 * NENC, 128)), 256, 0, sB>>>(
        posx1, D1, Wih1, D1, bih1, gid1, 3 * D1, SY1 * NENC, 3 * D1, D1);
    hy_kernel<<<4096, 256, 0, sB>>>(gid1, ghd1, h1a, hy1, D1, SY1);

    // ---- join: both output accumulations serialized on main stream (no race) ----
    cudaEventRecord(g_sp.ea, sA);
    cudaEventRecord(g_sp.eb, sB);
    cudaStreamWaitEvent(0, g_sp.ea, 0);
    cudaStreamWaitEvent(0, g_sp.eb, 0);
    gemm_nt<2><<<dim3(1, ceildiv(SY0 * NROWS, 64)), 256>>>(
        hy0, D0, Wpred0, D0, bpred0, nullptr, 0, SY0 * NROWS, S0, D0, out, S0);
    gemm_nt<2><<<dim3(1, ceildiv(SY1 * NROWS, 64)), 256>>>(
        hy1, D1, Wpred1, D1, bpred1, nullptr, 0, SY1 * NROWS, S1, D1, out, S1);
}

// round 16
// speedup vs baseline: 1.0551x; 1.0551x over previous
#include <cuda_runtime.h>
#include <math.h>

// ---------------- problem constants ----------------
#define NB    32
#define NSEQ  720
#define NPRED 96
#define NENC  321
#define NROWS (NB * NENC)      // 10272 sequences

#define D0 512
#define S0 48
#define T0 15
#define SY0 2

#define D1 256
#define S1 24
#define T1 4                   // only segments 0..3 are ever consumed
#define STEPS1 60
#define SY1 4

// ---------------- scratch (device globals) ----------------
__device__ __align__(16) float g_xc   [NROWS * NSEQ];
__device__ __align__(16) float g_xe0  [(size_t)T0 * NROWS * D0];
__device__ __align__(16) float g_gi0  [(size_t)T0 * NROWS * 3 * D0];
__device__ __align__(16) float g_h0a  [NROWS * D0];
__device__ __align__(16) float g_h0b  [NROWS * D0];
__device__ __align__(16) float g_xe1  [(size_t)T1 * NROWS * D1];
__device__ __align__(16) float g_gi1  [(size_t)T1 * NROWS * 3 * D1];
__device__ __align__(16) float g_h1a  [NROWS * D1];
__device__ __align__(16) float g_h1b  [NROWS * D1];
__device__ __align__(16) float g_ghd0 [NROWS * 3 * D0];
__device__ __align__(16) float g_gid0 [SY0 * NENC * 3 * D0];
__device__ __align__(16) float g_posx0[SY0 * NENC * D0];
__device__ __align__(16) float g_hy0  [(size_t)SY0 * NROWS * D0];
__device__ __align__(16) float g_ghd1 [NROWS * 3 * D1];
__device__ __align__(16) float g_gid1 [SY1 * NENC * 3 * D1];
__device__ __align__(16) float g_posx1[SY1 * NENC * D1];
__device__ __align__(16) float g_hy1  [(size_t)SY1 * NROWS * D1];

// ---------------- streams/events (created at static-init) ----------------
struct StreamPack {
    cudaStream_t a, b;
    cudaEvent_t root, ea, eb;
    StreamPack() {
        cudaStreamCreateWithFlags(&a, cudaStreamNonBlocking);
        cudaStreamCreateWithFlags(&b, cudaStreamNonBlocking);
        cudaEventCreateWithFlags(&root, cudaEventDisableTiming);
        cudaEventCreateWithFlags(&ea, cudaEventDisableTiming);
        cudaEventCreateWithFlags(&eb, cudaEventDisableTiming);
    }
};
static StreamPack g_sp;

// ---------------- mma / cp.async helpers ----------------
__device__ __forceinline__ void mma8(float c[4], unsigned a0, unsigned a1, unsigned a2,
                                     unsigned a3, unsigned b0, unsigned b1) {
    asm volatile(
        "mma.sync.aligned.m16n8k8.row.col.f32.tf32.tf32.f32 "
        "{%0,%1,%2,%3},{%4,%5,%6,%7},{%8,%9},{%0,%1,%2,%3};"
        : "+f"(c[0]), "+f"(c[1]), "+f"(c[2]), "+f"(c[3])
        : "r"(a0), "r"(a1), "r"(a2), "r"(a3), "r"(b0), "r"(b1));
}
__device__ __forceinline__ void cp16(void* sm, const void* gp, bool pred) {
    unsigned sa = (unsigned)__cvta_generic_to_shared(sm);
    int sz = pred ? 16 : 0;
    asm volatile("cp.async.cg.shared.global [%0], [%1], 16, %2;\n"
                 :: "r"(sa), "l"(gp), "r"(sz));
}
__device__ __forceinline__ void cp_commit() {
    asm volatile("cp.async.commit_group;\n");
}
template <int N>
__device__ __forceinline__ void cp_wait() {
    asm volatile("cp.async.wait_group %0;\n" :: "n"(N));
}

// ---------------- prep: xc[n][t] = x[b][t][e] - x[b][719][e] ----------------
__global__ void prep_kernel(const float* __restrict__ x) {
    __shared__ float tile[32][33];
    int b  = blockIdx.z;
    int t0 = blockIdx.x * 32;
    int e0 = blockIdx.y * 32;
    int tx = threadIdx.x, ty = threadIdx.y;   // (32, 8)
    int e_r = e0 + tx;
    float last = 0.f;
    if (e_r < NENC) last = x[((size_t)b * NSEQ + (NSEQ - 1)) * NENC + e_r];
    #pragma unroll
    for (int l = 0; l < 32; l += 8) {
        int t = t0 + ty + l;
        if (t < NSEQ && e_r < NENC)
            tile[ty + l][tx] = x[((size_t)b * NSEQ + t) * NENC + e_r] - last;
    }
    __syncthreads();
    int t_w = t0 + tx;
    #pragma unroll
    for (int l = 0; l < 32; l += 8) {
        int e = e0 + ty + l;
        if (e < NENC && t_w < NSEQ)
            g_xc[((size_t)b * NENC + e) * NSEQ + t_w] = tile[tx][ty + l];
    }
}

// ---------------- out init ----------------
__global__ void outinit_kernel(const float* __restrict__ x, float* __restrict__ out) {
    int idx = blockIdx.x * blockDim.x + threadIdx.x;
    if (idx >= NB * NPRED * NENC) return;
    int b = idx / (NPRED * NENC);
    int e = idx % NENC;
    out[idx] = x[((size_t)b * NSEQ + (NSEQ - 1)) * NENC + e];
}

// ---------------- embedding (fp32 SIMT; small K) ----------------
template <int SLEN>
__global__ __launch_bounds__(256) void embed_kernel(const float* __restrict__ Wemb,
                                                    const float* __restrict__ bemb,
                                                    float* __restrict__ xe, int d) {
    __shared__ float As[64][SLEN];
    __shared__ float Ws[64][SLEN + 1];
    int seg = blockIdx.z;
    int m0  = blockIdx.x * 64;
    int c0  = blockIdx.y * 64;
    int tid = threadIdx.x;
    for (int e = tid; e < 64 * SLEN; e += 256) {
        int r = e / SLEN, k = e % SLEN;
        int n = m0 + r;
        As[r][k] = (n < NROWS) ? g_xc[(size_t)n * NSEQ + seg * SLEN + k] : 0.f;
    }
    for (int e = tid; e < 64 * SLEN; e += 256) {
        int r = e / SLEN, k = e % SLEN;
        Ws[r][k] = Wemb[(size_t)(c0 + r) * SLEN + k];
    }
    __syncthreads();
    int tx = tid % 16, ty = tid / 16;
    float acc[4][4] = {};
    for (int k = 0; k < SLEN; k++) {
        float a[4], w[4];
        #pragma unroll
        for (int i = 0; i < 4; i++) a[i] = As[ty * 4 + i][k];
        #pragma unroll
        for (int j = 0; j < 4; j++) w[j] = Ws[tx * 4 + j][k];
        #pragma unroll
        for (int i = 0; i < 4; i++)
            #pragma unroll
            for (int j = 0; j < 4; j++) acc[i][j] += a[i] * w[j];
    }
    #pragma unroll
    for (int i = 0; i < 4; i++) {
        int n = m0 + ty * 4 + i;
        if (n >= NROWS) continue;
        #pragma unroll
        for (int j = 0; j < 4; j++) {
            int c = c0 + tx * 4 + j;
            float v = acc[i][j] + bemb[c];
            xe[((size_t)seg * NROWS + n) * d + c] = v > 0.f ? v : 0.f;
        }
    }
}

// ---------------- SIMT GEMM (MODE 2 = scatter-accumulate 0.5*v into output) ----------------
template <int MODE>
__global__ __launch_bounds__(256) void gemm_nt(const float* __restrict__ A, int lda,
                                               const float* __restrict__ Bw, int ldb,
                                               const float* __restrict__ bias,
                                               float* __restrict__ C, int ldc,
                                               int M, int Ncols, int K,
                                               float* __restrict__ out, int s_len) {
    __shared__ float As[16][64 + 4];
    __shared__ float Bs[16][64 + 4];
    int m0  = blockIdx.y * 64;
    int c0  = blockIdx.x * 64;
    int tid = threadIdx.x;
    int tx  = tid % 16, ty = tid / 16;
    int lr  = tid / 4;
    int lk  = (tid % 4) * 4;
    const float* Aptr = A + (size_t)(m0 + lr) * lda + lk;
    const float* Bptr = Bw + (size_t)(c0 + lr) * ldb + lk;
    bool a_ok = (m0 + lr) < M;
    bool b_ok = (c0 + lr) < Ncols;
    float acc[4][4] = {};
    for (int k0 = 0; k0 < K; k0 += 16) {
        float4 av = a_ok ? *(const float4*)(Aptr + k0) : make_float4(0, 0, 0, 0);
        float4 bv = b_ok ? *(const float4*)(Bptr + k0) : make_float4(0, 0, 0, 0);
        As[lk + 0][lr] = av.x; As[lk + 1][lr] = av.y; As[lk + 2][lr] = av.z; As[lk + 3][lr] = av.w;
        Bs[lk + 0][lr] = bv.x; Bs[lk + 1][lr] = bv.y; Bs[lk + 2][lr] = bv.z; Bs[lk + 3][lr] = bv.w;
        __syncthreads();
        #pragma unroll
        for (int kk = 0; kk < 16; kk++) {
            float a[4], b[4];
            #pragma unroll
            for (int i = 0; i < 4; i++) a[i] = As[kk][ty * 4 + i];
            #pragma unroll
            for (int j = 0; j < 4; j++) b[j] = Bs[kk][tx * 4 + j];
            #pragma unroll
            for (int i = 0; i < 4; i++)
                #pragma unroll
                for (int j = 0; j < 4; j++) acc[i][j] += a[i] * b[j];
        }
        __syncthreads();
    }
    #pragma unroll
    for (int i = 0; i < 4; i++) {
        int m = m0 + ty * 4 + i;
        if (m >= M) continue;
        #pragma unroll
        for (int j = 0; j < 4; j++) {
            int c = c0 + tx * 4 + j;
            if (c >= Ncols) continue;
            float v = acc[i][j] + (bias ? bias[c] : 0.f);
            if (MODE == 0) {
                C[(size_t)m * ldc + c] = v;
            } else {
                int sy = m / NROWS;
                int n  = m % NROWS;
                int b  = n / NENC, e = n % NENC;
                int p  = sy * s_len + c;
                out[((size_t)b * NPRED + p) * NENC + e] += 0.5f * v;
            }
        }
    }
}

// ---------------- tf32 GEMM, BK=16, 3-stage cp.async pipeline (dyn smem) ----------------
// C = A·Bw^T + bias. A [M,K] rm, Bw [Ncols,K] rm. BM=BN=128, 256 thr.
#define GEMM_SMEM (3 * 128 * 20 * 4 * 2)    // 61440
__global__ __launch_bounds__(256) void gemm_tf32(const float* __restrict__ A, int lda,
                                                 const float* __restrict__ Bw, int ldb,
                                                 const float* __restrict__ bias,
                                                 float* __restrict__ C, int ldc,
                                                 int M, int Ncols, int K) {
    extern __shared__ __align__(16) unsigned dyn_sm[];
    unsigned* Asb = dyn_sm;                      // [3][128][20]
    unsigned* Bsb = dyn_sm + 3 * 128 * 20;       // [3][128][20]
    #define AS(s, r, k) Asb[((s) * 128 + (r)) * 20 + (k)]
    #define BS(s, r, k) Bsb[((s) * 128 + (r)) * 20 + (k)]
    int m0 = blockIdx.y * 128, c0 = blockIdx.x * 128;
    int tid = threadIdx.x, lane = tid & 31, warp = tid >> 5;
    int g = lane >> 2, tig = lane & 3;
    int wm = (warp >> 2) * 64, wn = (warp & 3) * 32;
    float acc[4][4][4] = {};

    int r0l = tid >> 2, kcl = (tid & 3) * 4;
    int r1l = r0l + 64;
    const float* Ap0 = A + (size_t)(m0 + r0l) * lda + kcl;
    const float* Ap1 = A + (size_t)(m0 + r1l) * lda + kcl;
    const float* Bp0 = Bw + (size_t)(c0 + r0l) * ldb + kcl;
    const float* Bp1 = Bw + (size_t)(c0 + r1l) * ldb + kcl;
    bool a0ok = (m0 + r0l) < M, a1ok = (m0 + r1l) < M;
    bool b0ok = (c0 + r0l) < Ncols, b1ok = (c0 + r1l) < Ncols;

    int nit = K / 16;
    // prefetch stages 0,1
    #pragma unroll
    for (int p = 0; p < 2; p++) {
        if (p < nit) {
            int koff = p * 16;
            cp16(&AS(p, r0l, kcl), Ap0 + koff, a0ok);
            cp16(&AS(p, r1l, kcl), Ap1 + koff, a1ok);
            cp16(&BS(p, r0l, kcl), Bp0 + koff, b0ok);
            cp16(&BS(p, r1l, kcl), Bp1 + koff, b1ok);
        }
        cp_commit();
    }

    for (int it = 0; it < nit; it++) {
        if (it + 2 < nit) {
            int koff = (it + 2) * 16;
            int nb = (it + 2) % 3;
            cp16(&AS(nb, r0l, kcl), Ap0 + koff, a0ok);
            cp16(&AS(nb, r1l, kcl), Ap1 + koff, a1ok);
            cp16(&BS(nb, r0l, kcl), Bp0 + koff, b0ok);
            cp16(&BS(nb, r1l, kcl), Bp1 + koff, b1ok);
            cp_commit();
            cp_wait<2>();
        } else if (it + 1 < nit) {
            cp_wait<1>();
        } else {
            cp_wait<0>();
        }
        __syncthreads();
        int cb = it % 3;
        #pragma unroll
        for (int ks = 0; ks < 2; ks++) {
            unsigned af[4][4];
            #pragma unroll
            for (int mt = 0; mt < 4; mt++) {
                int r = wm + mt * 16 + g;
                af[mt][0] = AS(cb, r, ks * 8 + tig);
                af[mt][1] = AS(cb, r + 8, ks * 8 + tig);
                af[mt][2] = AS(cb, r, ks * 8 + tig + 4);
                af[mt][3] = AS(cb, r + 8, ks * 8 + tig + 4);
            }
            #pragma unroll
            for (int nt = 0; nt < 4; nt++) {
                int cc = wn + nt * 8 + g;
                unsigned b0 = BS(cb, cc, ks * 8 + tig);
                unsigned b1 = BS(cb, cc, ks * 8 + tig + 4);
                #pragma unroll
                for (int mt = 0; mt < 4; mt++)
                    mma8(acc[mt][nt], af[mt][0], af[mt][1], af[mt][2], af[mt][3], b0, b1);
            }
        }
        __syncthreads();
    }

    #pragma unroll
    for (int mt = 0; mt < 4; mt++)
        #pragma unroll
        for (int rh = 0; rh < 2; rh++) {
            int m = m0 + wm + mt * 16 + g + rh * 8;
            if (m >= M) continue;
            #pragma unroll
            for (int nt = 0; nt < 4; nt++) {
                int c = c0 + wn + nt * 8 + tig * 2;
                if (c >= Ncols) continue;
                float v0 = acc[mt][nt][rh * 2 + 0] + (bias ? bias[c] : 0.f);
                if (c + 1 < Ncols) {
                    float v1 = acc[mt][nt][rh * 2 + 1] + (bias ? bias[c + 1] : 0.f);
                    *(float2*)(C + (size_t)m * ldc + c) = make_float2(v0, v1);
                } else {
                    C[(size_t)m * ldc + c] = v0;
                }
            }
        }
    #undef AS
    #undef BS
}

// ---------------- fused tf32 GRU step, BK=16, 3-stage pipeline (dyn smem) ----------------
// gh = h_in·Whh^T (3 gates) via tensor cores, then gate math + h update.
// BM=64 rows, BN=64 cols, 256 thr (warps 2x4, warp tile 32x16).
#define GRU_SMEM (3 * (64 * 20 + 3 * 64 * 20) * 4)   // 61440
template <int D>
__global__ __launch_bounds__(256) void gru_step_tf32(const float* __restrict__ h_in,
                                                     const float* __restrict__ Whh,
                                                     const float* __restrict__ bhh,
                                                     const float* __restrict__ gi,
                                                     float* __restrict__ h_out, int M) {
    extern __shared__ __align__(16) unsigned dyn_sm[];
    unsigned* Hsb = dyn_sm;                      // [3][64][20]
    unsigned* Wsb = dyn_sm + 3 * 64 * 20;        // [3][3][64][20]
    #define HSX(s, r, k) Hsb[((s) * 64 + (r)) * 20 + (k)]
    #define WSX(s, gg, r, k) Wsb[(((s) * 3 + (gg)) * 64 + (r)) * 20 + (k)]
    int m0 = blockIdx.y * 64, c0 = blockIdx.x * 64;
    int tid = threadIdx.x, lane = tid & 31, warp = tid >> 5;
    int g = lane >> 2, tig = lane & 3;
    int wm = (warp >> 2) * 32, wn = (warp & 3) * 16;
    float acc[3][2][2][4] = {};

    int r_st = tid >> 2, kc_st = (tid & 3) * 4;
    const float* Hp = h_in + (size_t)(m0 + r_st) * D + kc_st;
    const float* Wp0 = Whh + (size_t)(0 * D + c0 + r_st) * D + kc_st;
    const float* Wp1 = Whh + (size_t)(1 * D + c0 + r_st) * D + kc_st;
    const float* Wp2 = Whh + (size_t)(2 * D + c0 + r_st) * D + kc_st;
    bool hok = (m0 + r_st) < M;

    const int nit = D / 16;
    #pragma unroll
    for (int p = 0; p < 2; p++) {
        if (p < nit) {
            int koff = p * 16;
            cp16(&HSX(p, r_st, kc_st), Hp + koff, hok);
            cp16(&WSX(p, 0, r_st, kc_st), Wp0 + koff, true);
            cp16(&WSX(p, 1, r_st, kc_st), Wp1 + koff, true);
            cp16(&WSX(p, 2, r_st, kc_st), Wp2 + koff, true);
        }
        cp_commit();
    }

    for (int it = 0; it < nit; it++) {
        if (it + 2 < nit) {
            int koff = (it + 2) * 16;
            int nb = (it + 2) % 3;
            cp16(&HSX(nb, r_st, kc_st), Hp + koff, hok);
            cp16(&WSX(nb, 0, r_st, kc_st), Wp0 + koff, true);
            cp16(&WSX(nb, 1, r_st, kc_st), Wp1 + koff, true);
            cp16(&WSX(nb, 2, r_st, kc_st), Wp2 + koff, true);
            cp_commit();
            cp_wait<2>();
        } else if (it + 1 < nit) {
            cp_wait<1>();
        } else {
            cp_wait<0>();
        }
        __syncthreads();
        int cb = it % 3;
        #pragma unroll
        for (int ks = 0; ks < 2; ks++) {
            unsigned af[2][4];
            #pragma unroll
            for (int mt = 0; mt < 2; mt++) {
                int r = wm + mt * 16 + g;
                af[mt][0] = HSX(cb, r, ks * 8 + tig);
                af[mt][1] = HSX(cb, r + 8, ks * 8 + tig);
                af[mt][2] = HSX(cb, r, ks * 8 + tig + 4);
                af[mt][3] = HSX(cb, r + 8, ks * 8 + tig + 4);
            }
            #pragma unroll
            for (int gate = 0; gate < 3; gate++)
                #pragma unroll
                for (int nt = 0; nt < 2; nt++) {
                    int cc = wn + nt * 8 + g;
                    unsigned b0 = WSX(cb, gate, cc, ks * 8 + tig);
                    unsigned b1 = WSX(cb, gate, cc, ks * 8 + tig + 4);
                    #pragma unroll
                    for (int mt = 0; mt < 2; mt++)
                        mma8(acc[gate][mt][nt], af[mt][0], af[mt][1], af[mt][2], af[mt][3],
                             b0, b1);
                }
        }
        __syncthreads();
    }

    float2 br[2], bz[2], bn[2];
    #pragma unroll
    for (int nt = 0; nt < 2; nt++) {
        int c = c0 + wn + nt * 8 + tig * 2;
        br[nt] = *(const float2*)(bhh + c);
        bz[nt] = *(const float2*)(bhh + D + c);
        bn[nt] = *(const float2*)(bhh + 2 * D + c);
    }

    #pragma unroll
    for (int mt = 0; mt < 2; mt++)
        #pragma unroll
        for (int rh = 0; rh < 2; rh++) {
            int m = m0 + wm + mt * 16 + g + rh * 8;
            if (m >= M) continue;
            const float* gim = gi + (size_t)m * 3 * D;
            #pragma unroll
            for (int nt = 0; nt < 2; nt++) {
                int c = c0 + wn + nt * 8 + tig * 2;
                float2 vr = *(const float2*)(gim + c);
                float2 vz = *(const float2*)(gim + D + c);
                float2 vn = *(const float2*)(gim + 2 * D + c);
                float2 hh = *(const float2*)(h_in + (size_t)m * D + c);
                float ar0 = acc[0][mt][nt][rh * 2 + 0], ar1 = acc[0][mt][nt][rh * 2 + 1];
                float az0 = acc[1][mt][nt][rh * 2 + 0], az1 = acc[1][mt][nt][rh * 2 + 1];
                float an0 = acc[2][mt][nt][rh * 2 + 0], an1 = acc[2][mt][nt][rh * 2 + 1];
                float r0 = 1.f / (1.f + __expf(-(vr.x + ar0 + br[nt].x)));
                float r1 = 1.f / (1.f + __expf(-(vr.y + ar1 + br[nt].y)));
                float z0 = 1.f / (1.f + __expf(-(vz.x + az0 + bz[nt].x)));
                float z1 = 1.f / (1.f + __expf(-(vz.y + az1 + bz[nt].y)));
                float n0 = tanhf(vn.x + r0 * (an0 + bn[nt].x));
                float n1 = tanhf(vn.y + r1 * (an1 + bn[nt].y));
                float o0 = (1.f - z0) * n0 + z0 * hh.x;
                float o1 = (1.f - z1) * n1 + z1 * hh.y;
                *(float2*)(h_out + (size_t)m * D + c) = make_float2(o0, o1);
            }
        }
    #undef HSX
    #undef WSX
}

// ---------------- decoder position rows ----------------
__global__ void posx_kernel(const float* __restrict__ pos, const float* __restrict__ chan,
                            float* __restrict__ posx, int D, int S) {
    int total = S * NENC * D;
    for (int idx = blockIdx.x * blockDim.x + threadIdx.x; idx < total;
         idx += gridDim.x * blockDim.x) {
        int r = idx / D, j = idx % D;
        int sy = r / NENC, e = r % NENC;
        int half = D / 2;
        posx[idx] = (j < half) ? pos[sy * half + j] : chan[e * half + (j - half)];
    }
}

// ---------------- decoder combine ----------------
__global__ void hy_kernel(const float* __restrict__ gid, const float* __restrict__ ghd,
                          const float* __restrict__ hfin, float* __restrict__ hy,
                          int D, int S) {
    size_t total = (size_t)S * NROWS * D;
    for (size_t idx = (size_t)blockIdx.x * blockDim.x + threadIdx.x; idx < total;
         idx += (size_t)gridDim.x * blockDim.x) {
        int j   = (int)(idx % D);
        size_t r = idx / D;
        int n   = (int)(r % NROWS);
        int sy  = (int)(r / NROWS);
        int e   = n % NENC;
        const float* gi = gid + (size_t)(sy * NENC + e) * 3 * D;
        const float* gh = ghd + (size_t)n * 3 * D;
        float rr = 1.f / (1.f + __expf(-(gi[j] + gh[j])));
        float zz = 1.f / (1.f + __expf(-(gi[D + j] + gh[D + j])));
        float nn = tanhf(gi[2 * D + j] + rr * gh[2 * D + j]);
        float h  = hfin[(size_t)n * D + j];
        hy[idx]  = (1.f - zz) * nn + zz * h;
    }
}

// ---------------- host orchestration (fork-join, two layers in parallel) ----------------
static inline int ceildiv(int a, int b) { return (a + b - 1) / b; }

extern "C" void kernel_launch(void* const* d_in, const int* in_sizes, int n_in,
                              void* d_out, int out_size) {
    const float* x      = (const float*)d_in[0];
    const float* Wemb0  = (const float*)d_in[1];
    const float* bemb0  = (const float*)d_in[2];
    const float* Wih0   = (const float*)d_in[3];
    const float* Whh0   = (const float*)d_in[4];
    const float* bih0   = (const float*)d_in[5];
    const float* bhh0   = (const float*)d_in[6];
    const float* Wpred0 = (const float*)d_in[7];
    const float* bpred0 = (const float*)d_in[8];
    const float* pos0   = (const float*)d_in[9];
    const float* chan0  = (const float*)d_in[10];
    const float* Wemb1  = (const float*)d_in[11];
    const float* bemb1  = (const float*)d_in[12];
    const float* Wih1   = (const float*)d_in[13];
    const float* Whh1   = (const float*)d_in[14];
    const float* bih1   = (const float*)d_in[15];
    const float* bhh1   = (const float*)d_in[16];
    const float* Wpred1 = (const float*)d_in[17];
    const float* bpred1 = (const float*)d_in[18];
    const float* pos1   = (const float*)d_in[19];
    const float* chan1  = (const float*)d_in[20];
    float* out = (float*)d_out;

    float *xe0, *gi0, *h0a, *h0b, *xe1, *gi1, *h1a, *h1b;
    float *ghd0, *gid0, *posx0, *hy0, *ghd1, *gid1, *posx1, *hy1;
    cudaGetSymbolAddress((void**)&xe0, g_xe0);
    cudaGetSymbolAddress((void**)&gi0, g_gi0);
    cudaGetSymbolAddress((void**)&h0a, g_h0a);
    cudaGetSymbolAddress((void**)&h0b, g_h0b);
    cudaGetSymbolAddress((void**)&xe1, g_xe1);
    cudaGetSymbolAddress((void**)&gi1, g_gi1);
    cudaGetSymbolAddress((void**)&h1a, g_h1a);
    cudaGetSymbolAddress((void**)&h1b, g_h1b);
    cudaGetSymbolAddress((void**)&ghd0, g_ghd0);
    cudaGetSymbolAddress((void**)&gid0, g_gid0);
    cudaGetSymbolAddress((void**)&posx0, g_posx0);
    cudaGetSymbolAddress((void**)&hy0, g_hy0);
    cudaGetSymbolAddress((void**)&ghd1, g_ghd1);
    cudaGetSymbolAddress((void**)&gid1, g_gid1);
    cudaGetSymbolAddress((void**)&posx1, g_posx1);
    cudaGetSymbolAddress((void**)&hy1, g_hy1);

    // raise dynamic smem caps (idempotent host-side calls; capture-legal)
    cudaFuncSetAttribute(gemm_tf32, cudaFuncAttributeMaxDynamicSharedMemorySize, GEMM_SMEM);
    cudaFuncSetAttribute(gru_step_tf32<D0>, cudaFuncAttributeMaxDynamicSharedMemorySize, GRU_SMEM);
    cudaFuncSetAttribute(gru_step_tf32<D1>, cudaFuncAttributeMaxDynamicSharedMemorySize, GRU_SMEM);

    cudaStream_t sA = g_sp.a, sB = g_sp.b;
    int rb64  = ceildiv(NROWS, 64);    // 161
    int rb128 = ceildiv(NROWS, 128);   // 81

    // ---- prologue on main stream: xc + out init ----
    prep_kernel<<<dim3(ceildiv(NSEQ, 32), ceildiv(NENC, 32), NB), dim3(32, 8)>>>(x);
    outinit_kernel<<<ceildiv(NB * NPRED * NENC, 256), 256>>>(x, out);

    // ---- fork ----
    cudaEventRecord(g_sp.root, 0);
    cudaStreamWaitEvent(sA, g_sp.root, 0);
    cudaStreamWaitEvent(sB, g_sp.root, 0);

    // ---------- layer 0 chain on stream A ----------
    embed_kernel<S0><<<dim3(rb64, D0 / 64, T0), 256, 0, sA>>>(Wemb0, bemb0, xe0, D0);
    gemm_tf32<<<dim3(3 * D0 / 128, ceildiv(T0 * NROWS, 128)), 256, GEMM_SMEM, sA>>>(
        xe0, D0, Wih0, D0, bih0, gi0, 3 * D0, T0 * NROWS, 3 * D0, D0);
    cudaMemsetAsync(h0a, 0, (size_t)NROWS * D0 * sizeof(float), sA);
    {
        float* hin = h0a; float* hout = h0b;
        for (int t = 0; t < T0; t++) {
            gru_step_tf32<D0><<<dim3(D0 / 64, rb64), 256, GRU_SMEM, sA>>>(
                hin, Whh0, bhh0, gi0 + (size_t)t * NROWS * 3 * D0, hout, NROWS);
            float* tmp = hin; hin = hout; hout = tmp;
        }
        gemm_tf32<<<dim3(3 * D0 / 128, rb128), 256, GEMM_SMEM, sA>>>(
            hin, D0, Whh0, D0, bhh0, ghd0, 3 * D0, NROWS, 3 * D0, D0);
        posx_kernel<<<ceildiv(SY0 * NENC * D0, 256), 256, 0, sA>>>(pos0, chan0, posx0, D0, SY0);
        gemm_tf32<<<dim3(3 * D0 / 128, ceildiv(SY0 * NENC, 128)), 256, GEMM_SMEM, sA>>>(
            posx0, D0, Wih0, D0, bih0, gid0, 3 * D0, SY0 * NENC, 3 * D0, D0);
        hy_kernel<<<4096, 256, 0, sA>>>(gid0, ghd0, hin, hy0, D0, SY0);
    }

    // ---------- layer 1 chain on stream B ----------
    embed_kernel<S1><<<dim3(rb64, D1 / 64, T1), 256, 0, sB>>>(Wemb1, bemb1, xe1, D1);
    gemm_tf32<<<dim3(3 * D1 / 128, ceildiv(T1 * NROWS, 128)), 256, GEMM_SMEM, sB>>>(
        xe1, D1, Wih1, D1, bih1, gi1, 3 * D1, T1 * NROWS, 3 * D1, D1);
    cudaMemsetAsync(h1a, 0, (size_t)NROWS * D1 * sizeof(float), sB);
    {
        float* hin = h1a; float* hout = h1b;
        for (int t = 0; t < STEPS1; t++) {
            int seg = t & 3;
            gru_step_tf32<D1><<<dim3(D1 / 64, rb64), 256, GRU_SMEM, sB>>>(
                hin, Whh1, bhh1, gi1 + (size_t)seg * NROWS * 3 * D1, hout, NROWS);
            float* tmp = hin; hin = hout; hout = tmp;
        }
        gemm_tf32<<<dim3(3 * D1 / 128, rb128), 256, GEMM_SMEM, sB>>>(
            hin, D1, Whh1, D1, bhh1, ghd1, 3 * D1, NROWS, 3 * D1, D1);
        posx_kernel<<<ceildiv(SY1 * NENC * D1, 256), 256, 0, sB>>>(pos1, chan1, posx1, D1, SY1);
        gemm_tf32<<<dim3(3 * D1 / 128, ceildiv(SY1 * NENC, 128)), 256, GEMM_SMEM, sB>>>(
            posx1, D1, Wih1, D1, bih1, gid1, 3 * D1, SY1 * NENC, 3 * D1, D1);
        hy_kernel<<<4096, 256, 0, sB>>>(gid1, ghd1, hin, hy1, D1, SY1);
    }

    // ---- join: both output accumulations serialized on main stream (no race) ----
    cudaEventRecord(g_sp.ea, sA);
    cudaEventRecord(g_sp.eb, sB);
    cudaStreamWaitEvent(0, g_sp.ea, 0);
    cudaStreamWaitEvent(0, g_sp.eb, 0);
    gemm_nt<2><<<dim3(1, ceildiv(SY0 * NROWS, 64)), 256>>>(
        hy0, D0, Wpred0, D0, bpred0, nullptr, 0, SY0 * NROWS, S0, D0, out, S0);
    gemm_nt<2><<<dim3(1, ceildiv(SY1 * NROWS, 64)), 256>>>(
        hy1, D1, Wpred1, D1, bpred1, nullptr, 0, SY1 * NROWS, S1, D1, out, S1);
}